// round 1
// baseline (speedup 1.0000x reference)
#include <cuda_runtime.h>

// Model_35347580846430: reflect-pad depthwise moving average, W=25, PAD=12
// x: [B=64, T=4096, N=128] f32, out same shape.
// out[b,t,n] = mean_{k=-12..12} x[b, reflect(t+k), n]

#define B_DIM 64
#define T_DIM 4096
#define N_DIM 128
#define PAD   12
#define WIN   25
#define CHUNK 64          // t-steps per thread
#define TY    8           // chunks per block (blockDim.y)

// N as float4: 32 groups
#define N4 (N_DIM / 4)

__device__ __forceinline__ int reflect_idx(int t) {
    // np.pad 'reflect': x[-1] -> x[1], x[T] -> x[T-2]
    t = (t < 0) ? -t : t;
    t = (t >= T_DIM) ? (2 * (T_DIM - 1) - t) : t;
    return t;
}

__global__ __launch_bounds__(32 * TY)
void ma25_kernel(const float4* __restrict__ x, float4* __restrict__ out) {
    const int tx    = threadIdx.x;                       // 0..31 -> float4 group over N
    const int chunk = blockIdx.x * TY + threadIdx.y;     // which t-chunk
    const int b     = blockIdx.y;
    const int t0    = chunk * CHUNK;

    const float4* __restrict__ xb = x   + (size_t)b * T_DIM * N4 + tx;
    float4*       __restrict__ ob = out + (size_t)b * T_DIM * N4 + tx;

    // Initial window sum centered at t0: t in [t0-12, t0+12]
    float sx = 0.f, sy = 0.f, sz = 0.f, sw = 0.f;
    #pragma unroll
    for (int k = -PAD; k <= PAD; k++) {
        int t = reflect_idx(t0 + k);
        float4 v = xb[(size_t)t * N4];
        sx += v.x; sy += v.y; sz += v.z; sw += v.w;
    }

    const float inv = 1.0f / (float)WIN;
    {
        float4 o; o.x = sx * inv; o.y = sy * inv; o.z = sz * inv; o.w = sw * inv;
        ob[(size_t)t0 * N4] = o;
    }

    // Slide the window across the rest of the chunk.
    #pragma unroll 4
    for (int i = 1; i < CHUNK; i++) {
        const int t = t0 + i;
        int tin  = t + PAD;      if (tin  >= T_DIM) tin  = 2 * (T_DIM - 1) - tin;
        int tout = t - PAD - 1;  if (tout < 0)      tout = -tout;

        float4 a = xb[(size_t)tin  * N4];
        float4 d = xb[(size_t)tout * N4];
        sx += a.x - d.x;
        sy += a.y - d.y;
        sz += a.z - d.z;
        sw += a.w - d.w;

        float4 o; o.x = sx * inv; o.y = sy * inv; o.z = sz * inv; o.w = sw * inv;
        ob[(size_t)t * N4] = o;
    }
}

extern "C" void kernel_launch(void* const* d_in, const int* in_sizes, int n_in,
                              void* d_out, int out_size) {
    const float4* x = (const float4*)d_in[0];
    float4* out = (float4*)d_out;

    dim3 block(32, TY);                       // 256 threads
    dim3 grid(T_DIM / CHUNK / TY, B_DIM);     // (8, 64) = 512 blocks
    ma25_kernel<<<grid, block>>>(x, out);
}

// round 2
// speedup vs baseline: 1.0145x; 1.0145x over previous
#include <cuda_runtime.h>

// Model_35347580846430: reflect-pad depthwise moving average, W=25, PAD=12
// x: [B=64, T=4096, N=128] f32, out same shape.
// out[b,t,n] = mean_{k=-12..12} x[b, reflect(t+k), n]
//
// R2: split N across 2 warps per (b,chunk) via float2 lanes -> 8192 warps
//     (~55/SM, 86% occ) to saturate HBM. CHUNK stays 64 (halo amp unchanged).

#define B_DIM 64
#define T_DIM 4096
#define N_DIM 128
#define PAD   12
#define WIN   25
#define CHUNK 64          // t-steps per thread
#define TY    4           // chunks per block (blockDim.y)

// N as float2: 64 groups (2 warps' worth of lanes)
#define N2 (N_DIM / 2)

__device__ __forceinline__ int reflect_idx(int t) {
    // np.pad 'reflect': x[-1] -> x[1], x[T] -> x[T-2]
    t = (t < 0) ? -t : t;
    t = (t >= T_DIM) ? (2 * (T_DIM - 1) - t) : t;
    return t;
}

__global__ __launch_bounds__(64 * TY)
void ma25_kernel(const float2* __restrict__ x, float2* __restrict__ out) {
    const int tx    = threadIdx.x;                       // 0..63 -> float2 group over N
    const int chunk = blockIdx.x * TY + threadIdx.y;     // which t-chunk
    const int b     = blockIdx.y;
    const int t0    = chunk * CHUNK;

    const float2* __restrict__ xb = x   + (size_t)b * T_DIM * N2 + tx;
    float2*       __restrict__ ob = out + (size_t)b * T_DIM * N2 + tx;

    // Initial window sum centered at t0: t in [t0-12, t0+12]
    float sx = 0.f, sy = 0.f;
    #pragma unroll
    for (int k = -PAD; k <= PAD; k++) {
        int t = reflect_idx(t0 + k);
        float2 v = xb[(size_t)t * N2];
        sx += v.x; sy += v.y;
    }

    const float inv = 1.0f / (float)WIN;
    {
        float2 o; o.x = sx * inv; o.y = sy * inv;
        ob[(size_t)t0 * N2] = o;
    }

    // Slide the window across the rest of the chunk.
    #pragma unroll 8
    for (int i = 1; i < CHUNK; i++) {
        const int t = t0 + i;
        int tin  = t + PAD;      if (tin  >= T_DIM) tin  = 2 * (T_DIM - 1) - tin;
        int tout = t - PAD - 1;  if (tout < 0)      tout = -tout;

        float2 a = xb[(size_t)tin  * N2];
        float2 d = xb[(size_t)tout * N2];
        sx += a.x - d.x;
        sy += a.y - d.y;

        float2 o; o.x = sx * inv; o.y = sy * inv;
        ob[(size_t)t * N2] = o;
    }
}

extern "C" void kernel_launch(void* const* d_in, const int* in_sizes, int n_in,
                              void* d_out, int out_size) {
    const float2* x = (const float2*)d_in[0];
    float2* out = (float2*)d_out;

    dim3 block(64, TY);                            // 256 threads, 8 warps
    dim3 grid(T_DIM / CHUNK / TY, B_DIM);          // (16, 64) = 1024 blocks
    ma25_kernel<<<grid, block>>>(x, out);
}